// round 1
// baseline (speedup 1.0000x reference)
#include <cuda_runtime.h>
#include <math.h>

// Problem constants (fixed shapes from reference setup_inputs)
#define B_   4
#define DK   128
#define DV   512
#define LM   4096
#define LQ   4096
#define SCALE 0.08838834764831843f   // 1/sqrt(128)

// Column-sum scratch (softmax denominators), later holds reciprocals.
__device__ float g_colsum[B_ * LQ];

__global__ void zero_colsum_k() {
    int i = blockIdx.x * blockDim.x + threadIdx.x;
    if (i < B_ * LQ) g_colsum[i] = 0.0f;
}

__global__ void recip_colsum_k() {
    int i = blockIdx.x * blockDim.x + threadIdx.x;
    if (i < B_ * LQ) g_colsum[i] = 1.0f / g_colsum[i];
}

// ---------------------------------------------------------------------------
// GEMM1 + exp epilogue + per-column partial sums.
//   e[b,m,q] = exp( (sum_d mk[b,d,m]*qk[b,d,q]) * SCALE )
// Tile 128(m) x 128(q), K = DK = 128, BK = 8. 256 threads, 8x8 per thread.
// Both operands are K-major-outer / output-dim-contiguous => no transpose.
// ---------------------------------------------------------------------------
__global__ __launch_bounds__(256) void gemm1_exp_k(
    const float* __restrict__ mk, const float* __restrict__ qk,
    float* __restrict__ e_out)
{
    __shared__ float a_s[8][128];
    __shared__ float b_s[8][128];
    __shared__ float red[16][128];

    const int b   = blockIdx.z;
    const int m0  = blockIdx.y * 128;
    const int q0  = blockIdx.x * 128;
    const int tid = threadIdx.x;
    const int tx  = tid & 15;
    const int ty  = tid >> 4;

    const float* A  = mk + (size_t)b * DK * LM;   // A[d][m], m contiguous
    const float* Bq = qk + (size_t)b * DK * LQ;   // B[d][q], q contiguous

    const int lr = tid >> 5;          // 0..7  (k row)
    const int lc = (tid & 31) << 2;   // 0..124 (col, float4)

    float acc[8][8];
#pragma unroll
    for (int i = 0; i < 8; i++)
#pragma unroll
        for (int j = 0; j < 8; j++) acc[i][j] = 0.0f;

    for (int k0 = 0; k0 < DK; k0 += 8) {
        *(float4*)&a_s[lr][lc] = *(const float4*)&A[(size_t)(k0 + lr) * LM + m0 + lc];
        *(float4*)&b_s[lr][lc] = *(const float4*)&Bq[(size_t)(k0 + lr) * LQ + q0 + lc];
        __syncthreads();
#pragma unroll
        for (int k = 0; k < 8; k++) {
            float4 a0 = *(float4*)&a_s[k][ty * 8];
            float4 a1 = *(float4*)&a_s[k][ty * 8 + 4];
            float4 b0 = *(float4*)&b_s[k][tx * 8];
            float4 b1 = *(float4*)&b_s[k][tx * 8 + 4];
            float af[8] = {a0.x, a0.y, a0.z, a0.w, a1.x, a1.y, a1.z, a1.w};
            float bf[8] = {b0.x, b0.y, b0.z, b0.w, b1.x, b1.y, b1.z, b1.w};
#pragma unroll
            for (int i = 0; i < 8; i++)
#pragma unroll
                for (int j = 0; j < 8; j++) acc[i][j] += af[i] * bf[j];
        }
        __syncthreads();
    }

    // Epilogue: exp, store e, accumulate per-q partial sums
    float qsum[8];
#pragma unroll
    for (int j = 0; j < 8; j++) qsum[j] = 0.0f;

    float* ep = e_out + ((size_t)b * LM + m0) * LQ + q0;
#pragma unroll
    for (int i = 0; i < 8; i++) {
        float ev[8];
#pragma unroll
        for (int j = 0; j < 8; j++) {
            ev[j] = expf(acc[i][j] * SCALE);
            qsum[j] += ev[j];
        }
        float4 v0 = make_float4(ev[0], ev[1], ev[2], ev[3]);
        float4 v1 = make_float4(ev[4], ev[5], ev[6], ev[7]);
        size_t row = (size_t)(ty * 8 + i) * LQ;
        *(float4*)&ep[row + tx * 8]     = v0;
        *(float4*)&ep[row + tx * 8 + 4] = v1;
    }

    // Block-wide reduce over ty, then one atomicAdd per q column
#pragma unroll
    for (int j = 0; j < 8; j++) red[ty][tx * 8 + j] = qsum[j];
    __syncthreads();
    for (int s = 8; s > 0; s >>= 1) {
        if (ty < s) {
#pragma unroll
            for (int j = 0; j < 8; j++)
                red[ty][tx * 8 + j] += red[ty + s][tx * 8 + j];
        }
        __syncthreads();
    }
    if (ty == 0) {
#pragma unroll
        for (int j = 0; j < 8; j++)
            atomicAdd(&g_colsum[b * LQ + q0 + tx * 8 + j], red[0][tx * 8 + j]);
    }
}

// ---------------------------------------------------------------------------
// GEMM2: mem[b,v,q] = (sum_m mv[b,v,m] * e[b,m,q]) * invsum[b,q]
// Tile 128(v) x 128(q), K = LM = 4096, BK = 16. 256 threads, 8x8 per thread.
// Grid x = v-tiles (innermost) so concurrent v-tiles reuse e tiles in L2.
// ---------------------------------------------------------------------------
__global__ __launch_bounds__(256) void gemm2_k(
    const float* __restrict__ mv, const float* __restrict__ e_in,
    float* __restrict__ mem_out)
{
    __shared__ float a_s[16][132];   // [k][v], padded
    __shared__ float b_s[16][128];   // [k][q]

    const int b   = blockIdx.z;
    const int v0  = blockIdx.x * 128;
    const int q0  = blockIdx.y * 128;
    const int tid = threadIdx.x;
    const int tx  = tid & 15;
    const int ty  = tid >> 4;

    const float* A = mv  + ((size_t)b * DV + v0) * LM;   // A[v][m], m contiguous
    const float* E = e_in + ((size_t)b * LM) * LQ + q0;  // E[m][q], q contiguous

    float acc[8][8];
#pragma unroll
    for (int i = 0; i < 8; i++)
#pragma unroll
        for (int j = 0; j < 8; j++) acc[i][j] = 0.0f;

    for (int k0 = 0; k0 < LM; k0 += 16) {
        // A tile: 128 v x 16 m, transposed into a_s[k][v]
#pragma unroll
        for (int t = 0; t < 2; t++) {
            int f  = tid * 2 + t;        // 0..511
            int v  = f >> 2;             // 0..127
            int kk = (f & 3) << 2;       // 0,4,8,12
            float4 av = *(const float4*)&A[(size_t)v * LM + k0 + kk];
            a_s[kk + 0][v] = av.x;
            a_s[kk + 1][v] = av.y;
            a_s[kk + 2][v] = av.z;
            a_s[kk + 3][v] = av.w;
        }
        // B tile: 16 m x 128 q (coalesced float4)
#pragma unroll
        for (int t = 0; t < 2; t++) {
            int kk = (tid >> 5) + 8 * t; // 0..15
            int q  = (tid & 31) << 2;    // 0..124
            *(float4*)&b_s[kk][q] = *(const float4*)&E[(size_t)(k0 + kk) * LQ + q];
        }
        __syncthreads();
#pragma unroll
        for (int k = 0; k < 16; k++) {
            float4 a0 = *(float4*)&a_s[k][ty * 8];
            float4 a1 = *(float4*)&a_s[k][ty * 8 + 4];
            float4 b0 = *(float4*)&b_s[k][tx * 8];
            float4 b1 = *(float4*)&b_s[k][tx * 8 + 4];
            float af[8] = {a0.x, a0.y, a0.z, a0.w, a1.x, a1.y, a1.z, a1.w};
            float bf[8] = {b0.x, b0.y, b0.z, b0.w, b1.x, b1.y, b1.z, b1.w};
#pragma unroll
            for (int i = 0; i < 8; i++)
#pragma unroll
                for (int j = 0; j < 8; j++) acc[i][j] += af[i] * bf[j];
        }
        __syncthreads();
    }

    // Epilogue: scale by reciprocal column sums, write mem
    float inv[8];
#pragma unroll
    for (int j = 0; j < 8; j++) inv[j] = g_colsum[b * LQ + q0 + tx * 8 + j];

    float* O = mem_out + ((size_t)b * DV + v0) * LQ + q0;
#pragma unroll
    for (int i = 0; i < 8; i++) {
        float4 v0w = make_float4(acc[i][0] * inv[0], acc[i][1] * inv[1],
                                 acc[i][2] * inv[2], acc[i][3] * inv[3]);
        float4 v1w = make_float4(acc[i][4] * inv[4], acc[i][5] * inv[5],
                                 acc[i][6] * inv[6], acc[i][7] * inv[7]);
        size_t row = (size_t)(ty * 8 + i) * LQ;
        *(float4*)&O[row + tx * 8]     = v0w;
        *(float4*)&O[row + tx * 8 + 4] = v1w;
    }
}

// ---------------------------------------------------------------------------
// Normalize p in place: p[b,m,q] *= invsum[b,q]   (vectorized float4)
// ---------------------------------------------------------------------------
__global__ void normalize_p_k(float* __restrict__ p) {
    size_t i4 = (size_t)blockIdx.x * blockDim.x + threadIdx.x;
    size_t e0 = i4 * 4;                       // element index (LQ % 4 == 0)
    int q = (int)(e0 & (LQ - 1));
    int b = (int)(e0 >> 24);                  // LM*LQ = 2^24
    float4 v = *(float4*)&p[e0];
    float4 s = *(const float4*)&g_colsum[b * LQ + q];
    v.x *= s.x; v.y *= s.y; v.z *= s.z; v.w *= s.w;
    *(float4*)&p[e0] = v;
}

// ---------------------------------------------------------------------------
extern "C" void kernel_launch(void* const* d_in, const int* in_sizes, int n_in,
                              void* d_out, int out_size) {
    const float* mk = (const float*)d_in[0];   // [B, DK, LM]
    const float* mv = (const float*)d_in[1];   // [B, DV, LM]
    const float* qk = (const float*)d_in[2];   // [B, DK, LQ]

    float* mem = (float*)d_out;                                  // [B, DV, LQ]
    float* p   = (float*)d_out + (size_t)B_ * DV * LQ;           // [B, LM, LQ]

    zero_colsum_k<<<(B_ * LQ + 255) / 256, 256>>>();

    dim3 g1(LQ / 128, LM / 128, B_);
    gemm1_exp_k<<<g1, 256>>>(mk, qk, p);

    recip_colsum_k<<<(B_ * LQ + 255) / 256, 256>>>();

    dim3 g2(DV / 128, LQ / 128, B_);   // v-tiles innermost for L2 reuse of e
    gemm2_k<<<g2, 256>>>(mv, p, mem);

    normalize_p_k<<<(int)(((size_t)B_ * LM * LQ / 4) / 256), 256>>>(p);
}

// round 4
// speedup vs baseline: 1.6203x; 1.6203x over previous
#include <cuda_runtime.h>
#include <cuda_fp16.h>
#include <cstdint>
#include <math.h>

// Problem constants
#define B_   4
#define DK   128
#define DV   512
#define LM   4096
#define LQ   4096
#define SCALE 0.08838834764831843f   // 1/sqrt(128)

// ---------------------------------------------------------------------------
// Scratch (static __device__ — no allocation allowed)
// e split into f16 hi/lo, stored TRANSPOSED: e_T[b][q][m]  (m contiguous)
// mv split into f16 hi/lo, natural layout   mv[b][v][m]    (m contiguous)
// ---------------------------------------------------------------------------
__device__ __half g_ehi[(size_t)B_ * LQ * LM];
__device__ __half g_elo[(size_t)B_ * LQ * LM];
__device__ __half g_vhi[(size_t)B_ * DV * LM];
__device__ __half g_vlo[(size_t)B_ * DV * LM];
__device__ float  g_colsum[B_ * LQ];

__device__ __forceinline__ uint32_t smem_to_u32(const void* p) {
    uint32_t a;
    asm("{ .reg .u64 t; cvta.to.shared.u64 t, %1; cvt.u32.u64 %0, t; }"
        : "=r"(a) : "l"(p));
    return a;
}

// ldmatrix x4: four 8x8 f16 tiles (base-ISA, sm_75+)
__device__ __forceinline__ void ldsm4(uint32_t* r, uint32_t addr) {
    asm volatile("ldmatrix.sync.aligned.m8n8.x4.shared.b16 {%0,%1,%2,%3}, [%4];"
        : "=r"(r[0]), "=r"(r[1]), "=r"(r[2]), "=r"(r[3]) : "r"(addr));
}

// mma m16n8k16 f16 -> f32 accum (base-ISA, sm_80+)
__device__ __forceinline__ void mma16816(float* c, const uint32_t* a, const uint32_t* b) {
    asm volatile(
        "mma.sync.aligned.m16n8k16.row.col.f32.f16.f16.f32 "
        "{%0,%1,%2,%3}, {%4,%5,%6,%7}, {%8,%9}, {%0,%1,%2,%3};"
        : "+f"(c[0]), "+f"(c[1]), "+f"(c[2]), "+f"(c[3])
        : "r"(a[0]), "r"(a[1]), "r"(a[2]), "r"(a[3]), "r"(b[0]), "r"(b[1]));
}

// ---------------------------------------------------------------------------
// Small kernels
// ---------------------------------------------------------------------------
__global__ void zero_colsum_k() {
    int i = blockIdx.x * blockDim.x + threadIdx.x;
    if (i < B_ * LQ) g_colsum[i] = 0.0f;
}
__global__ void recip_colsum_k() {
    int i = blockIdx.x * blockDim.x + threadIdx.x;
    if (i < B_ * LQ) g_colsum[i] = 1.0f / g_colsum[i];
}

// Split mv (fp32) into f16 hi/lo, once. 4 elements per thread.
__global__ __launch_bounds__(256) void convert_mv_k(const float* __restrict__ mv) {
    size_t i4 = ((size_t)blockIdx.x * 256 + threadIdx.x) * 4;
    float4 v = *(const float4*)&mv[i4];
    __align__(8) __half hb[4], lb[4];
    float x;
    x = v.x; hb[0] = __float2half_rn(x); lb[0] = __float2half_rn(x - __half2float(hb[0]));
    x = v.y; hb[1] = __float2half_rn(x); lb[1] = __float2half_rn(x - __half2float(hb[1]));
    x = v.z; hb[2] = __float2half_rn(x); lb[2] = __float2half_rn(x - __half2float(hb[2]));
    x = v.w; hb[3] = __float2half_rn(x); lb[3] = __float2half_rn(x - __half2float(hb[3]));
    *(uint2*)&g_vhi[i4] = *(uint2*)hb;
    *(uint2*)&g_vlo[i4] = *(uint2*)lb;
}

// ---------------------------------------------------------------------------
// GEMM1 (SIMT fp32) + exp epilogue -> split f16 e, TRANSPOSED into e_T[q][m],
// plus per-q column sums. 128(m) x 128(q) tiles, K=DK=128.
// ---------------------------------------------------------------------------
__global__ __launch_bounds__(256) void gemm1_exp_k(
    const float* __restrict__ mk, const float* __restrict__ qk)
{
    __shared__ float a_s[8][128];
    __shared__ float b_s[8][128];
    __shared__ float red[16][128];

    const int b   = blockIdx.z;
    const int m0  = blockIdx.y * 128;
    const int q0  = blockIdx.x * 128;
    const int tid = threadIdx.x;
    const int tx  = tid & 15;
    const int ty  = tid >> 4;

    const float* A  = mk + (size_t)b * DK * LM;
    const float* Bq = qk + (size_t)b * DK * LQ;

    const int lr = tid >> 5;
    const int lc = (tid & 31) << 2;

    float acc[8][8];
#pragma unroll
    for (int i = 0; i < 8; i++)
#pragma unroll
        for (int j = 0; j < 8; j++) acc[i][j] = 0.0f;

    for (int k0 = 0; k0 < DK; k0 += 8) {
        *(float4*)&a_s[lr][lc] = *(const float4*)&A[(size_t)(k0 + lr) * LM + m0 + lc];
        *(float4*)&b_s[lr][lc] = *(const float4*)&Bq[(size_t)(k0 + lr) * LQ + q0 + lc];
        __syncthreads();
#pragma unroll
        for (int k = 0; k < 8; k++) {
            float4 a0 = *(float4*)&a_s[k][ty * 8];
            float4 a1 = *(float4*)&a_s[k][ty * 8 + 4];
            float4 b0 = *(float4*)&b_s[k][tx * 8];
            float4 b1 = *(float4*)&b_s[k][tx * 8 + 4];
            float af[8] = {a0.x, a0.y, a0.z, a0.w, a1.x, a1.y, a1.z, a1.w};
            float bf[8] = {b0.x, b0.y, b0.z, b0.w, b1.x, b1.y, b1.z, b1.w};
#pragma unroll
            for (int i = 0; i < 8; i++)
#pragma unroll
                for (int j = 0; j < 8; j++) acc[i][j] += af[i] * bf[j];
        }
        __syncthreads();
    }

    // exp in place + column sums
    float qsum[8];
#pragma unroll
    for (int j = 0; j < 8; j++) qsum[j] = 0.0f;
#pragma unroll
    for (int i = 0; i < 8; i++)
#pragma unroll
        for (int j = 0; j < 8; j++) {
            acc[i][j] = expf(acc[i][j] * SCALE);
            qsum[j] += acc[i][j];
        }

    // Split f16, write transposed: e_T[(b, q, m)] ; per j: 8 m-contiguous halves
    const size_t ebase = (size_t)b * LQ * LM;
#pragma unroll
    for (int j = 0; j < 8; j++) {
        __align__(16) __half hb[8], lb[8];
#pragma unroll
        for (int i = 0; i < 8; i++) {
            float e = acc[i][j];
            __half h = __float2half_rn(e);
            hb[i] = h;
            lb[i] = __float2half_rn(e - __half2float(h));
        }
        size_t off = ebase + (size_t)(q0 + tx * 8 + j) * LM + m0 + ty * 8;
        *(uint4*)&g_ehi[off] = *(uint4*)hb;
        *(uint4*)&g_elo[off] = *(uint4*)lb;
    }

    // block reduce over ty, atomicAdd per q column
#pragma unroll
    for (int j = 0; j < 8; j++) red[ty][tx * 8 + j] = qsum[j];
    __syncthreads();
    for (int s = 8; s > 0; s >>= 1) {
        if (ty < s) {
#pragma unroll
            for (int j = 0; j < 8; j++)
                red[ty][tx * 8 + j] += red[ty + s][tx * 8 + j];
        }
        __syncthreads();
    }
    if (ty == 0) {
#pragma unroll
        for (int j = 0; j < 8; j++)
            atomicAdd(&g_colsum[b * LQ + q0 + tx * 8 + j], red[0][tx * 8 + j]);
    }
}

// ---------------------------------------------------------------------------
// GEMM2 on mma.sync tensor cores:
//   mem[v][q] = (sum_m mv[v][m] * e[m][q]) * inv[q]
// f16 split operands, 3 terms (hi*hi + hi*lo + lo*hi), fp32 accum in regs.
// CTA 128(v) x 128(q), 8 warps in 4(m) x 2(n) grid -> warp tile 32x64.
// BK = 32 halves per iter; smem rows padded to 40 halves (ldmatrix-friendly).
// A = mv_split [v][m] row-major; B = e_split_T [q][m] = col-major => .row.col.
// ---------------------------------------------------------------------------
#define BKH 32
#define LDS 40   // smem row stride in halves

__global__ __launch_bounds__(256) void gemm2_mma_k(float* __restrict__ mem_out)
{
    __shared__ __half sAh[128 * LDS];
    __shared__ __half sAl[128 * LDS];
    __shared__ __half sBh[128 * LDS];
    __shared__ __half sBl[128 * LDS];

    const int tid  = threadIdx.x;
    const int wid  = tid >> 5;
    const int lane = tid & 31;
    const int b    = blockIdx.z;
    const int v0   = blockIdx.x * 128;
    const int q0   = blockIdx.y * 128;
    const int wm   = wid & 3;    // 0..3 -> m offset wm*32
    const int wn   = wid >> 2;   // 0..1 -> n offset wn*64

    const __half* Ahi = g_vhi + ((size_t)b * DV + v0) * LM;
    const __half* Alo = g_vlo + ((size_t)b * DV + v0) * LM;
    const __half* Bhi = g_ehi + ((size_t)b * LQ + q0) * LM;
    const __half* Blo = g_elo + ((size_t)b * LQ + q0) * LM;

    float acc[2][8][4];
#pragma unroll
    for (int mt = 0; mt < 2; mt++)
#pragma unroll
        for (int nt = 0; nt < 8; nt++)
#pragma unroll
            for (int e = 0; e < 4; e++) acc[mt][nt][e] = 0.0f;

    const uint32_t baseAh = smem_to_u32(sAh);
    const uint32_t baseAl = smem_to_u32(sAl);
    const uint32_t baseBh = smem_to_u32(sBh);
    const uint32_t baseBl = smem_to_u32(sBl);

    // ldmatrix lane address components (constant over the loop)
    const int a_row = wm * 32 + (lane & 15);        // + mt*16
    const int a_col = (lane >> 4) * 8;              // + ks*16
    const int b_row = wn * 64 + (lane & 7) + 8 * (lane >> 4);   // + np*16
    const int b_col = 8 * ((lane >> 3) & 1);        // + ks*16

    // staging slots: s = tid + p*256 (0..511); row = s>>2, chunk = (s&3)*8
    const int s0_row = tid >> 2;
    const int s0_ch  = (tid & 3) * 8;

    for (int it = 0; it < LM / BKH; ++it) {
        const int k0 = it * BKH;
#pragma unroll
        for (int p = 0; p < 2; ++p) {
            int row = s0_row + p * 64;
            int ch  = s0_ch;
            size_t goff = (size_t)row * LM + k0 + ch;
            int soff = row * LDS + ch;
            *(uint4*)&sAh[soff] = *(const uint4*)&Ahi[goff];
            *(uint4*)&sAl[soff] = *(const uint4*)&Alo[goff];
            *(uint4*)&sBh[soff] = *(const uint4*)&Bhi[goff];
            *(uint4*)&sBl[soff] = *(const uint4*)&Blo[goff];
        }
        __syncthreads();

#pragma unroll
        for (int ks = 0; ks < 2; ++ks) {
            const int kc = ks * 16;
            uint32_t ah[2][4], al[2][4];
#pragma unroll
            for (int mt = 0; mt < 2; ++mt) {
                uint32_t off = (uint32_t)(((a_row + mt * 16) * LDS + a_col + kc) * 2);
                ldsm4(ah[mt], baseAh + off);
                ldsm4(al[mt], baseAl + off);
            }
#pragma unroll
            for (int np = 0; np < 4; ++np) {
                uint32_t boff = (uint32_t)(((b_row + np * 16) * LDS + b_col + kc) * 2);
                uint32_t bh[4], bl[4];
                ldsm4(bh, baseBh + boff);
                ldsm4(bl, baseBl + boff);
#pragma unroll
                for (int mt = 0; mt < 2; ++mt) {
                    // term 1: hi*hi
                    mma16816(acc[mt][2 * np],     ah[mt], bh);
                    mma16816(acc[mt][2 * np + 1], ah[mt], bh + 2);
                    // term 2: hi*lo
                    mma16816(acc[mt][2 * np],     ah[mt], bl);
                    mma16816(acc[mt][2 * np + 1], ah[mt], bl + 2);
                    // term 3: lo*hi
                    mma16816(acc[mt][2 * np],     al[mt], bh);
                    mma16816(acc[mt][2 * np + 1], al[mt], bh + 2);
                }
            }
        }
        __syncthreads();
    }

    // Epilogue: scale by reciprocal column sums, write mem.
    // C frag: c0,c1 -> row lane/4, cols (lane%4)*2 + {0,1}; c2,c3 -> row+8.
    const int er = v0 + wm * 32 + (lane >> 2);
    const int ec = q0 + wn * 64 + (lane & 3) * 2;
#pragma unroll
    for (int mt = 0; mt < 2; ++mt) {
#pragma unroll
        for (int nt = 0; nt < 8; ++nt) {
            int row = er + mt * 16;
            int col = ec + nt * 8;
            float2 inv = *(const float2*)&g_colsum[b * LQ + col];
            float2 o0 = make_float2(acc[mt][nt][0] * inv.x, acc[mt][nt][1] * inv.y);
            float2 o1 = make_float2(acc[mt][nt][2] * inv.x, acc[mt][nt][3] * inv.y);
            *(float2*)&mem_out[((size_t)b * DV + row) * LQ + col]     = o0;
            *(float2*)&mem_out[((size_t)b * DV + row + 8) * LQ + col] = o1;
        }
    }
}

// ---------------------------------------------------------------------------
// Normalize + transpose: p[b][m][q] = (e_hi[b][q][m] + e_lo[b][q][m]) * inv[b][q]
// 64x64 tiles through SMEM, coalesced both sides.
// ---------------------------------------------------------------------------
__global__ __launch_bounds__(256) void normalize_p_k(float* __restrict__ p)
{
    __shared__ float t[64][65];
    const int b  = blockIdx.z;
    const int q0 = blockIdx.x * 64;
    const int m0 = blockIdx.y * 64;
    const int tid = threadIdx.x;
    const int tx = tid & 15;
    const int ty = tid >> 4;

#pragma unroll
    for (int pass = 0; pass < 4; ++pass) {
        int q = q0 + ty + pass * 16;
        size_t base = ((size_t)b * LQ + q) * LM + m0 + tx * 4;
        uint2 h = *(const uint2*)&g_ehi[base];
        uint2 l = *(const uint2*)&g_elo[base];
        float inv = g_colsum[b * LQ + q];
        float2 f0 = __half22float2(*(__half2*)&h.x);
        float2 f1 = __half22float2(*(__half2*)&h.y);
        float2 g0 = __half22float2(*(__half2*)&l.x);
        float2 g1 = __half22float2(*(__half2*)&l.y);
        int qc = ty + pass * 16;
        t[tx * 4 + 0][qc] = (f0.x + g0.x) * inv;
        t[tx * 4 + 1][qc] = (f0.y + g0.y) * inv;
        t[tx * 4 + 2][qc] = (f1.x + g1.x) * inv;
        t[tx * 4 + 3][qc] = (f1.y + g1.y) * inv;
    }
    __syncthreads();
#pragma unroll
    for (int pass = 0; pass < 4; ++pass) {
        int ml = ty + pass * 16;
        float4 v;
        v.x = t[ml][tx * 4 + 0];
        v.y = t[ml][tx * 4 + 1];
        v.z = t[ml][tx * 4 + 2];
        v.w = t[ml][tx * 4 + 3];
        *(float4*)&p[((size_t)b * LM + m0 + ml) * LQ + q0 + tx * 4] = v;
    }
}

// ---------------------------------------------------------------------------
extern "C" void kernel_launch(void* const* d_in, const int* in_sizes, int n_in,
                              void* d_out, int out_size) {
    const float* mk = (const float*)d_in[0];   // [B, DK, LM]
    const float* mv = (const float*)d_in[1];   // [B, DV, LM]
    const float* qk = (const float*)d_in[2];   // [B, DK, LQ]

    float* mem = (float*)d_out;                               // [B, DV, LQ]
    float* p   = (float*)d_out + (size_t)B_ * DV * LQ;        // [B, LM, LQ]

    zero_colsum_k<<<(B_ * LQ + 255) / 256, 256>>>();

    convert_mv_k<<<(int)(((size_t)B_ * DV * LM / 4) / 256), 256>>>(mv);

    dim3 g1(LQ / 128, LM / 128, B_);
    gemm1_exp_k<<<g1, 256>>>(mk, qk);

    recip_colsum_k<<<(B_ * LQ + 255) / 256, 256>>>();

    dim3 g2(DV / 128, LQ / 128, B_);   // v innermost -> adjacent CTAs share e tiles in L2
    gemm2_mma_k<<<g2, 256>>>(mem);

    dim3 g3(LQ / 64, LM / 64, B_);
    normalize_p_k<<<g3, 256>>>(p);
}